// round 17
// baseline (speedup 1.0000x reference)
#include <cuda_runtime.h>
#include <cuda_bf16.h>

#define N_NODES 50000
#define IN_CH   64
#define REL_DIM 32
#define N_EDGES 800000
#define NEG_SLOPE 0.01f

#define NBLK   888            // k1: 6 blocks/SM x 148 SMs — all co-resident
#define NTHR   256
#define GT     (NBLK * NTHR)
#define GWARPS (NBLK * 8)
#define NCHUNK ((N_NODES + 255) / 256)   // 196
#define NBAR   6
#define NGRP   ((N_NODES + 3) / 4)              // 12500 4-node groups
#define GBLK   ((NGRP + 7) / 8)                 // 1563 blocks for gather kernels
#define ET     ((N_EDGES + 255) / 256)          // 3125

// ---------------- scratch ----------------
__device__ float    g_ew1  [N_EDGES];
__device__ float    g_ew2  [N_EDGES];
__device__ float    g_alpha[N_EDGES];
__device__ float    g_x    [N_NODES * IN_CH];
__device__ float    g_x2   [N_NODES * IN_CH];
__device__ float    g_h    [N_NODES * IN_CH];
__device__ float    g_ai   [N_NODES];
__device__ float    g_aj   [N_NODES];
__device__ unsigned g_mkey1[N_NODES];
__device__ float    g_ssum1[N_NODES];
__device__ unsigned g_mkey2[N_NODES];
__device__ float    g_ssum2[N_NODES];
__device__ int      g_deg  [N_NODES];
__device__ int      g_rowst[N_NODES];
__device__ int      g_curs [N_NODES];
__device__ int2     g_rowdeg[N_NODES];         // {start, deg}
__device__ int      g_bsum [NCHUNK];
__device__ int      g_boff [NCHUNK];
__device__ int2     g_edge [N_EDGES];          // {src, eid} in dst-CSR order
__device__ float    g_v1   [REL_DIM];
__device__ float    g_v2   [REL_DIM];
__device__ float    g_ewc  [2];
__device__ unsigned gA[NBAR];
__device__ unsigned gD[NBAR];

struct SmemXF { float Wt[IN_CH * IN_CH]; float bsh[IN_CH], ais[IN_CH], ajs[IN_CH]; };
struct SmemGT { float Wse[REL_DIM * 32]; float Wso[REL_DIM * 32]; float Bs[IN_CH]; };
struct SmemEW { float sv1[REL_DIM], sv2[REL_DIM], sc[2]; };
struct SmemSC { int wsum[8]; };
union SmemK1 { SmemXF xf; SmemEW ew; SmemSC sc; };
union SmemK2 { SmemXF xf; SmemGT gt; };

__device__ __forceinline__ unsigned fkey(float f) {
    unsigned b = __float_as_uint(f);
    return (b & 0x80000000u) ? ~b : (b | 0x80000000u);
}
__device__ __forceinline__ float funkey(unsigned u) {
    unsigned b = (u & 0x80000000u) ? (u & 0x7fffffffu) : ~u;
    return __uint_as_float(b);
}

// ---- software grid barrier (k1 only) --------------------------------------------
__device__ __forceinline__ void gsync(int id) {
    __syncthreads();
    if (threadIdx.x == 0) {
        __threadfence();
        atomicAdd(&gA[id], 1u);
        while (*((volatile unsigned*)&gA[id]) < (unsigned)NBLK) __nanosleep(64);
        unsigned d = atomicAdd(&gD[id], 1u);
        if (d == (unsigned)(NBLK - 1)) {
            *((volatile unsigned*)&gA[id]) = 0u;
            *((volatile unsigned*)&gD[id]) = 0u;
        }
        __threadfence();
    }
    __syncthreads();
}

// =================================================================================
// k1: setup + layer-1 attention (persistent)
// =================================================================================
__global__ void __launch_bounds__(NTHR, 6)
k1_setup(const float* __restrict__ feat, const int* __restrict__ src, const int* __restrict__ dst,
         const float* __restrict__ r, const float* __restrict__ relW, const float* __restrict__ relB,
         const float* c1_lw, const float* c1_lb, const float* c1_aiw, const float* c1_aib,
         const float* c1_ajw, const float* c1_ajb, const float* c1_eww, const float* c1_ewb,
         const float* c2_eww, const float* c2_ewb)
{
    __shared__ SmemK1 sm;
    int tid  = threadIdx.x;
    int blk  = blockIdx.x;
    int gtid = blk * NTHR + tid;
    int lane = tid & 31;
    int gwarp = blk * 8 + (tid >> 5);

    // ---------------- P0: init + ewvec ----------------
    for (int i = gtid; i < N_NODES; i += GT) {
        g_deg[i] = 0;
        g_mkey1[i] = 0u; g_ssum1[i] = 0.0f;
        g_mkey2[i] = 0u; g_ssum2[i] = 0.0f;
    }
    if (blk == 0) {
        int t = tid;
        if (t < REL_DIM) {
            float a1 = 0.f, a2 = 0.f;
#pragma unroll
            for (int c = 0; c < IN_CH; c++) {
                float w = relW[c * REL_DIM + t];
                a1 += w * c1_eww[c];
                a2 += w * c2_eww[c];
            }
            g_v1[t] = a1; g_v2[t] = a2;
        } else if (t == 32) {
            float s = 0.f;
            for (int c = 0; c < IN_CH; c++) s += relB[c] * c1_eww[c];
            g_ewc[0] = s + c1_ewb[0];
        } else if (t == 33) {
            float s = 0.f;
            for (int c = 0; c < IN_CH; c++) s += relB[c] * c2_eww[c];
            g_ewc[1] = s + c2_ewb[0];
        }
    }
    gsync(0);

    // ---------------- P1: ew_hist (edges) + transform L1 (nodes) ----------------
    if (tid < REL_DIM) { sm.ew.sv1[tid] = g_v1[tid]; sm.ew.sv2[tid] = g_v2[tid]; }
    if (tid < 2) sm.ew.sc[tid] = g_ewc[tid];
    __syncthreads();
    {
        float c0 = sm.ew.sc[0], c1 = sm.ew.sc[1];
        for (int e = gtid; e < N_EDGES; e += GT) {
            const float4* rp = reinterpret_cast<const float4*>(r + (size_t)e * REL_DIM);
            float a1 = 0.f, a2 = 0.f;
#pragma unroll
            for (int q = 0; q < 8; q++) {
                float4 f = rp[q];
                a1 += f.x * sm.ew.sv1[4*q] + f.y * sm.ew.sv1[4*q+1] + f.z * sm.ew.sv1[4*q+2] + f.w * sm.ew.sv1[4*q+3];
                a2 += f.x * sm.ew.sv2[4*q] + f.y * sm.ew.sv2[4*q+1] + f.z * sm.ew.sv2[4*q+2] + f.w * sm.ew.sv2[4*q+3];
            }
            g_ew1[e] = a1 + c0;
            g_ew2[e] = a2 + c1;
            atomicAdd(&g_deg[dst[e]], 1);
        }
    }
    __syncthreads();
    // transform L1 (warp per node)
    for (int i = tid; i < IN_CH * IN_CH; i += NTHR) {
        int c = i >> 6, k = i & 63;
        sm.xf.Wt[k * IN_CH + c] = c1_lw[i];
    }
    if (tid < IN_CH) { sm.xf.bsh[tid] = c1_lb[tid]; sm.xf.ais[tid] = c1_aiw[tid]; sm.xf.ajs[tid] = c1_ajw[tid]; }
    float aib0 = c1_aib[0], ajb0 = c1_ajb[0];
    __syncthreads();
    for (int n = gwarp; n < N_NODES; n += GWARPS) {
        float iv0 = feat[(size_t)n * IN_CH + lane];
        float iv1 = feat[(size_t)n * IN_CH + 32 + lane];
        float acc0 = sm.xf.bsh[lane], acc1 = sm.xf.bsh[32 + lane];
#pragma unroll
        for (int k = 0; k < 32; k++) {
            float v = __shfl_sync(0xffffffffu, iv0, k);
            acc0 += v * sm.xf.Wt[k * IN_CH + lane];
            acc1 += v * sm.xf.Wt[k * IN_CH + 32 + lane];
        }
#pragma unroll
        for (int k = 0; k < 32; k++) {
            float v = __shfl_sync(0xffffffffu, iv1, k);
            acc0 += v * sm.xf.Wt[(k + 32) * IN_CH + lane];
            acc1 += v * sm.xf.Wt[(k + 32) * IN_CH + 32 + lane];
        }
        g_x[(size_t)n * IN_CH + lane]      = acc0;
        g_x[(size_t)n * IN_CH + 32 + lane] = acc1;
        float ap = acc0 * sm.xf.ais[lane] + acc1 * sm.xf.ais[32 + lane];
        float jp = acc0 * sm.xf.ajs[lane] + acc1 * sm.xf.ajs[32 + lane];
#pragma unroll
        for (int o = 16; o > 0; o >>= 1) {
            ap += __shfl_xor_sync(0xffffffffu, ap, o);
            jp += __shfl_xor_sync(0xffffffffu, jp, o);
        }
        if (lane == 0) { g_ai[n] = ap + aib0; g_aj[n] = jp + ajb0; }
    }
    gsync(1);

    // ---------------- P2: scan1 + alpha_max L1 ----------------
    if (blk < NCHUNK) {
        int i = blk * 256 + tid;
        int v = (i < N_NODES) ? g_deg[i] : 0;
        int x = v;
#pragma unroll
        for (int off = 1; off < 32; off <<= 1) {
            int y = __shfl_up_sync(0xffffffffu, x, off);
            if (lane >= off) x += y;
        }
        int wid = tid >> 5;
        if (lane == 31) sm.sc.wsum[wid] = x;
        __syncthreads();
        if (wid == 0) {
            int s = (lane < 8) ? sm.sc.wsum[lane] : 0;
#pragma unroll
            for (int off = 1; off < 8; off <<= 1) {
                int y = __shfl_up_sync(0xffffffffu, s, off);
                if (lane >= off) s += y;
            }
            if (lane < 8) sm.sc.wsum[lane] = s;
        }
        __syncthreads();
        int woff = (wid == 0) ? 0 : sm.sc.wsum[wid - 1];
        if (i < N_NODES) g_rowst[i] = woff + x - v;
        if (tid == 255) g_bsum[blk] = woff + x;
        __syncthreads();
    }
    for (int i = gtid; i < N_EDGES; i += GT) {
        int s = src[i], d = dst[i];
        float a = g_ai[d] + g_aj[s] + g_ew1[i];
        a = a > 0.0f ? a : NEG_SLOPE * a;
        g_alpha[i] = a;
        atomicMax(&g_mkey1[s], fkey(a));
    }
    gsync(2);

    // ---------------- P3: scan2 (block 0) + exp_sum L1 ----------------
    if (blk == 0) {
        int t = tid, wid = t >> 5;
        int v = (t < NCHUNK) ? g_bsum[t] : 0;
        int x = v;
#pragma unroll
        for (int off = 1; off < 32; off <<= 1) {
            int y = __shfl_up_sync(0xffffffffu, x, off);
            if (lane >= off) x += y;
        }
        if (lane == 31) sm.sc.wsum[wid] = x;
        __syncthreads();
        if (wid == 0) {
            int s = (lane < 8) ? sm.sc.wsum[lane] : 0;
#pragma unroll
            for (int off = 1; off < 8; off <<= 1) {
                int y = __shfl_up_sync(0xffffffffu, s, off);
                if (lane >= off) s += y;
            }
            if (lane < 8) sm.sc.wsum[lane] = s;
        }
        __syncthreads();
        int woff = (wid == 0) ? 0 : sm.sc.wsum[wid - 1];
        if (t < NCHUNK) g_boff[t] = woff + x - v;
        __syncthreads();
    }
    for (int i = gtid; i < N_EDGES; i += GT) {
        int s = src[i];
        float m = funkey(g_mkey1[s]);
        float ex = __expf(g_alpha[i] - m);
        g_alpha[i] = ex;
        atomicAdd(&g_ssum1[s], ex);
    }
    gsync(3);

    // ---------------- P4: scan3 (write curs + rowdeg) ----------------
    for (int i = gtid; i < N_NODES; i += GT) {
        int v = g_rowst[i] + g_boff[i >> 8];
        g_curs[i] = v;
        g_rowdeg[i] = make_int2(v, g_deg[i]);
    }
    gsync(4);

    // ---------------- P5: scatter ----------------
    for (int i = gtid; i < N_EDGES; i += GT) {
        int p = atomicAdd(&g_curs[dst[i]], 1);
        g_edge[p] = make_int2(src[i], i);
    }
}

// =================================================================================
// gather + fused rel-projection: ONE 4-node group per warp, headers prefetched
// =================================================================================
__device__ __forceinline__ void gather4(SmemGT* gt, const float* __restrict__ x,
                                        const float* __restrict__ r,
                                        const float* __restrict__ ssum,
                                        float* __restrict__ out, int n0, int lane)
{
    int2 rd[4];
#pragma unroll
    for (int i = 0; i < 4; i++) {
        int n = n0 + i;
        rd[i] = (n < N_NODES) ? g_rowdeg[n] : make_int2(0, 0);
    }
    // prefetch chunk-1 headers for all 4 nodes (independent latency chains)
    int ses[4], see[4];
    float cf[4];
#pragma unroll
    for (int i = 0; i < 4; i++) {
        ses[i] = 0; see[i] = 0; cf[i] = 0.f;
        int m = rd[i].y < 32 ? rd[i].y : 32;
        if (lane < m) {
            int2 se = g_edge[rd[i].x + lane];
            ses[i] = se.x; see[i] = se.y;
            cf[i] = __fdividef(g_alpha[se.y], ssum[se.x] + 1e-16f);
        }
    }

    float accx[4], accy[4], accr[4], csum[4];
#pragma unroll
    for (int i = 0; i < 4; i++) {
        accx[i] = 0.f; accy[i] = 0.f; accr[i] = 0.f; csum[i] = cf[i];
        int deg = rd[i].y;
        int m = deg < 32 ? deg : 32;
#pragma unroll 8
        for (int j = 0; j < 32; j++) {
            if (j < m) {
                float cj = __shfl_sync(0xffffffffu, cf[i],  j);
                int   sj = __shfl_sync(0xffffffffu, ses[i], j);
                int   ej = __shfl_sync(0xffffffffu, see[i], j);
                float2 xv = *reinterpret_cast<const float2*>(x + (size_t)sj * IN_CH + 2 * lane);
                accx[i] += cj * xv.x;
                accy[i] += cj * xv.y;
                accr[i] += cj * r[(size_t)ej * REL_DIM + lane];
            }
        }
        // rare tail for deg > 32
        for (int base = 32; base < deg; base += 32) {
            int m2 = deg - base; if (m2 > 32) m2 = 32;
            int s2 = 0, e2 = 0; float c2 = 0.f;
            if (lane < m2) {
                int2 se = g_edge[rd[i].x + base + lane];
                s2 = se.x; e2 = se.y;
                c2 = __fdividef(g_alpha[se.y], ssum[se.x] + 1e-16f);
            }
            csum[i] += c2;
#pragma unroll 8
            for (int j = 0; j < 32; j++) {
                if (j < m2) {
                    float cj = __shfl_sync(0xffffffffu, c2, j);
                    int   sj = __shfl_sync(0xffffffffu, s2, j);
                    int   ej = __shfl_sync(0xffffffffu, e2, j);
                    float2 xv = *reinterpret_cast<const float2*>(x + (size_t)sj * IN_CH + 2 * lane);
                    accx[i] += cj * xv.x;
                    accy[i] += cj * xv.y;
                    accr[i] += cj * r[(size_t)ej * REL_DIM + lane];
                }
            }
        }
#pragma unroll
        for (int o = 16; o > 0; o >>= 1)
            csum[i] += __shfl_xor_sync(0xffffffffu, csum[i], o);
    }

    // fused projection
#pragma unroll 8
    for (int k = 0; k < REL_DIM; k++) {
        float we = gt->Wse[k * 32 + lane];
        float wo = gt->Wso[k * 32 + lane];
#pragma unroll
        for (int i = 0; i < 4; i++) {
            float v = __shfl_sync(0xffffffffu, accr[i], k);
            accx[i] += v * we;
            accy[i] += v * wo;
        }
    }
    const float2* Bs2 = reinterpret_cast<const float2*>(gt->Bs);
    float2 bb = Bs2[lane];
#pragma unroll
    for (int i = 0; i < 4; i++) {
        int node = n0 + i;
        if (node < N_NODES) {
            float r0 = accx[i] + csum[i] * bb.x;
            float r1 = accy[i] + csum[i] * bb.y;
            *reinterpret_cast<float2*>(out + (size_t)node * IN_CH + 2 * lane) =
                make_float2(fmaxf(r0, 0.f), fmaxf(r1, 0.f));
        }
    }
}

__device__ __forceinline__ void fill_gt(SmemGT* gt, const float* __restrict__ relW,
                                        const float* __restrict__ relB)
{
    int tid = threadIdx.x;
    for (int i = tid; i < IN_CH * REL_DIM; i += NTHR) {
        int c = i >> 5, k = i & 31;
        if (c & 1) gt->Wso[k * 32 + (c >> 1)] = relW[i];
        else       gt->Wse[k * 32 + (c >> 1)] = relW[i];
    }
    if (tid < IN_CH) gt->Bs[tid] = relB[tid];
}

// ---- k2: gather L1 -> g_h, then transform L2 on the same warp's nodes -----------
__global__ void __launch_bounds__(NTHR, 3)
k2_g1x2(const float* __restrict__ r, const float* __restrict__ relW, const float* __restrict__ relB,
        const float* c2_lw, const float* c2_lb, const float* c2_aiw, const float* c2_aib,
        const float* c2_ajw, const float* c2_ajb)
{
    __shared__ SmemK2 sm;
    int tid = threadIdx.x, lane = tid & 31;
    int n0 = (blockIdx.x * 8 + (tid >> 5)) * 4;

    fill_gt(&sm.gt, relW, relB);
    __syncthreads();
    if (n0 < N_NODES)
        gather4(&sm.gt, g_x, r, g_ssum1, g_h, n0, lane);

    // transform L2 (same warp's nodes -> no grid sync needed)
    __syncthreads();
    for (int i = tid; i < IN_CH * IN_CH; i += NTHR) {
        int c = i >> 6, k = i & 63;
        sm.xf.Wt[k * IN_CH + c] = c2_lw[i];
    }
    if (tid < IN_CH) { sm.xf.bsh[tid] = c2_lb[tid]; sm.xf.ais[tid] = c2_aiw[tid]; sm.xf.ajs[tid] = c2_ajw[tid]; }
    float aib0 = c2_aib[0], ajb0 = c2_ajb[0];
    __syncthreads();

    if (n0 >= N_NODES) return;
    float iv0[4], iv1[4], acc0[4], acc1[4];
#pragma unroll
    for (int i = 0; i < 4; i++) {
        int n = n0 + i;
        bool ok = (n < N_NODES);
        iv0[i] = ok ? g_h[(size_t)n * IN_CH + lane] : 0.f;
        iv1[i] = ok ? g_h[(size_t)n * IN_CH + 32 + lane] : 0.f;
        acc0[i] = sm.xf.bsh[lane];
        acc1[i] = sm.xf.bsh[32 + lane];
    }
#pragma unroll 8
    for (int k = 0; k < 32; k++) {
        float w0 = sm.xf.Wt[k * IN_CH + lane];
        float w1 = sm.xf.Wt[k * IN_CH + 32 + lane];
#pragma unroll
        for (int i = 0; i < 4; i++) {
            float v = __shfl_sync(0xffffffffu, iv0[i], k);
            acc0[i] += v * w0;
            acc1[i] += v * w1;
        }
    }
#pragma unroll 8
    for (int k = 0; k < 32; k++) {
        float w0 = sm.xf.Wt[(k + 32) * IN_CH + lane];
        float w1 = sm.xf.Wt[(k + 32) * IN_CH + 32 + lane];
#pragma unroll
        for (int i = 0; i < 4; i++) {
            float v = __shfl_sync(0xffffffffu, iv1[i], k);
            acc0[i] += v * w0;
            acc1[i] += v * w1;
        }
    }
#pragma unroll
    for (int i = 0; i < 4; i++) {
        int n = n0 + i;
        if (n < N_NODES) {
            g_x2[(size_t)n * IN_CH + lane]      = acc0[i];
            g_x2[(size_t)n * IN_CH + 32 + lane] = acc1[i];
            float ap = acc0[i] * sm.xf.ais[lane] + acc1[i] * sm.xf.ais[32 + lane];
            float jp = acc0[i] * sm.xf.ajs[lane] + acc1[i] * sm.xf.ajs[32 + lane];
#pragma unroll
            for (int o = 16; o > 0; o >>= 1) {
                ap += __shfl_xor_sync(0xffffffffu, ap, o);
                jp += __shfl_xor_sync(0xffffffffu, jp, o);
            }
            if (lane == 0) { g_ai[n] = ap + aib0; g_aj[n] = jp + ajb0; }
        }
    }
}

// ---- k3a: alpha_max L2 ----------------------------------------------------------
__global__ void k3a_alpha2(const int* __restrict__ src, const int* __restrict__ dst)
{
    int i = blockIdx.x * 256 + threadIdx.x;
    if (i >= N_EDGES) return;
    int s = src[i], d = dst[i];
    float a = g_ai[d] + g_aj[s] + g_ew2[i];
    a = a > 0.0f ? a : NEG_SLOPE * a;
    g_alpha[i] = a;
    atomicMax(&g_mkey2[s], fkey(a));
}

// ---- k3b: exp_sum L2 ------------------------------------------------------------
__global__ void k3b_exp2(const int* __restrict__ src)
{
    int i = blockIdx.x * 256 + threadIdx.x;
    if (i >= N_EDGES) return;
    int s = src[i];
    float m = funkey(g_mkey2[s]);
    float ex = __expf(g_alpha[i] - m);
    g_alpha[i] = ex;
    atomicAdd(&g_ssum2[s], ex);
}

// ---- k4: gather L2 -> out -------------------------------------------------------
__global__ void __launch_bounds__(NTHR, 3)
k4_g2(const float* __restrict__ r, const float* __restrict__ relW, const float* __restrict__ relB,
      float* __restrict__ out)
{
    __shared__ SmemGT gt;
    int tid = threadIdx.x, lane = tid & 31;
    int n0 = (blockIdx.x * 8 + (tid >> 5)) * 4;
    fill_gt(&gt, relW, relB);
    __syncthreads();
    if (n0 < N_NODES)
        gather4(&gt, g_x2, r, g_ssum2, out, n0, lane);
}

extern "C" void kernel_launch(void* const* d_in, const int* in_sizes, int n_in,
                              void* d_out, int out_size)
{
    const float* feat   = (const float*)d_in[0];
    const int*   eidx   = (const int*)  d_in[1];
    const float* r      = (const float*)d_in[2];
    const float* rel_w  = (const float*)d_in[3];
    const float* rel_b  = (const float*)d_in[4];
    const float* c1_lw  = (const float*)d_in[5];
    const float* c1_lb  = (const float*)d_in[6];
    const float* c1_aiw = (const float*)d_in[7];
    const float* c1_aib = (const float*)d_in[8];
    const float* c1_ajw = (const float*)d_in[9];
    const float* c1_ajb = (const float*)d_in[10];
    const float* c1_eww = (const float*)d_in[11];
    const float* c1_ewb = (const float*)d_in[12];
    const float* c2_lw  = (const float*)d_in[13];
    const float* c2_lb  = (const float*)d_in[14];
    const float* c2_aiw = (const float*)d_in[15];
    const float* c2_aib = (const float*)d_in[16];
    const float* c2_ajw = (const float*)d_in[17];
    const float* c2_ajb = (const float*)d_in[18];
    const float* c2_eww = (const float*)d_in[19];
    const float* c2_ewb = (const float*)d_in[20];
    float* out = (float*)d_out;

    const int* src = eidx;
    const int* dst = eidx + N_EDGES;

    k1_setup<<<NBLK, NTHR>>>(feat, src, dst, r, rel_w, rel_b,
                             c1_lw, c1_lb, c1_aiw, c1_aib, c1_ajw, c1_ajb, c1_eww, c1_ewb,
                             c2_eww, c2_ewb);
    k2_g1x2<<<GBLK, NTHR>>>(r, rel_w, rel_b,
                            c2_lw, c2_lb, c2_aiw, c2_aib, c2_ajw, c2_ajb);
    k3a_alpha2<<<ET, NTHR>>>(src, dst);
    k3b_exp2<<<ET, NTHR>>>(src);
    k4_g2<<<GBLK, NTHR>>>(r, rel_w, rel_b, out);
}